// round 3
// baseline (speedup 1.0000x reference)
#include <cuda_runtime.h>
#include <cstdint>
#include <math.h>

// Problem constants
#define Bsz   1024
#define Tlen  80
#define Dd    512
#define Cc    78      // VOCAB+1
#define Mrows (Bsz*Tlen)   // 81920
#define BLANKI 77
#define PRED  30
#define LOGITS_ELEMS ((size_t)Mrows * Cc)  // 6,389,760

// argmax path scratch (static device global — no runtime alloc)
__device__ int g_best[Mrows];

// packed fp32x2 FMA: d = a*b + d (elementwise on 2 packed floats)
__device__ __forceinline__ void ffma2(unsigned long long& d,
                                      unsigned long long a,
                                      unsigned long long b) {
    asm("fma.rn.f32x2 %0, %1, %2, %0;" : "+l"(d) : "l"(a), "l"(b));
}

// ---------------------------------------------------------------------------
// Fused GEMM (exact fp32 via packed f32x2 FMA) + softmax + per-row argmax.
// Tile: 128 rows x 80 cols per CTA, BK=16, double-buffered smem.
// 256 threads, each computes an 8x5 tile as 4 row-pairs x 5 cols of FFMA2.
// A in smem is k-major (rows contiguous) -> row-pairs load as b64 directly.
// B in smem is stored duplicated {v,v} -> dup-pairs load as one LDS.64.
// ---------------------------------------------------------------------------
__global__ __launch_bounds__(256, 1)
void gemm_softmax_kernel(const float* __restrict__ feat,
                         const float* __restrict__ Wm,
                         const float* __restrict__ bias,
                         float* __restrict__ out)
{
    __shared__ union {
        struct {
            float feat[2][16][128];     // [stage][k][row]
            float w2[2][16][80][2];     // [stage][k][col][dup]
        } ld;
        float outs[128][81];            // epilogue staging
    } sm;
    __shared__ float bias_s[80];
    __shared__ float rmax[128];
    __shared__ float rinv[128];

    const int t  = threadIdx.x;
    const int tx = t & 15;        // col group: cols tx*5 .. tx*5+4
    const int ty = t >> 4;        // row group: rows ty*8 .. ty*8+7
    const int m0 = blockIdx.x * 128;

    if (t < 80) bias_s[t] = (t < Cc) ? bias[t] : 0.0f;

    unsigned long long acc[4][5];   // [row-pair][col], packed (row 2p, row 2p+1)
#pragma unroll
    for (int p = 0; p < 4; p++)
#pragma unroll
        for (int u = 0; u < 5; u++) acc[p][u] = 0ull;

    // ---- load chunk 0 into stage 0 ----
    {
#pragma unroll
        for (int i = 0; i < 2; i++) {
            int lid = t + 256 * i;
            int r = lid >> 2, kq = lid & 3;
            float4 v = *reinterpret_cast<const float4*>(feat + (size_t)(m0 + r) * Dd + kq * 4);
            sm.ld.feat[0][kq * 4 + 0][r] = v.x;
            sm.ld.feat[0][kq * 4 + 1][r] = v.y;
            sm.ld.feat[0][kq * 4 + 2][r] = v.z;
            sm.ld.feat[0][kq * 4 + 3][r] = v.w;
        }
#pragma unroll
        for (int i = 0; i < 5; i++) {
            int lid = t + 256 * i;
            int k = lid / 80, cc2 = lid - k * 80;
            float v = (cc2 < Cc) ? Wm[(size_t)k * Cc + cc2] : 0.0f;
            sm.ld.w2[0][k][cc2][0] = v;
            sm.ld.w2[0][k][cc2][1] = v;
        }
    }
    __syncthreads();

    // ---- main loop over 32 K-chunks, single-sync double buffer ----
    for (int ch = 0; ch < 32; ++ch) {
        const int s = ch & 1;
        float4 pf[2];
        float  pw[5];
        if (ch < 31) {
            const int kb = (ch + 1) * 16;
#pragma unroll
            for (int i = 0; i < 2; i++) {
                int lid = t + 256 * i;
                int r = lid >> 2, kq = lid & 3;
                pf[i] = *reinterpret_cast<const float4*>(feat + (size_t)(m0 + r) * Dd + kb + kq * 4);
            }
#pragma unroll
            for (int i = 0; i < 5; i++) {
                int lid = t + 256 * i;
                int k = lid / 80, cc2 = lid - k * 80;
                pw[i] = (cc2 < Cc) ? Wm[(size_t)(kb + k) * Cc + cc2] : 0.0f;
            }
        }

#pragma unroll
        for (int kk = 0; kk < 16; kk++) {
            // 4 row-pairs: rows ty*8 .. ty*8+7 (contiguous in smem, 16B aligned)
            const ulonglong2* ap =
                reinterpret_cast<const ulonglong2*>(&sm.ld.feat[s][kk][ty * 8]);
            ulonglong2 al = ap[0];
            ulonglong2 ah = ap[1];
            unsigned long long av[4] = { al.x, al.y, ah.x, ah.y };
            unsigned long long bd[5];
#pragma unroll
            for (int u = 0; u < 5; u++)
                bd[u] = *reinterpret_cast<const unsigned long long*>(
                            &sm.ld.w2[s][kk][tx * 5 + u][0]);
#pragma unroll
            for (int p = 0; p < 4; p++)
#pragma unroll
                for (int u = 0; u < 5; u++)
                    ffma2(acc[p][u], av[p], bd[u]);
        }

        if (ch < 31) {
            const int s2 = (ch + 1) & 1;
#pragma unroll
            for (int i = 0; i < 2; i++) {
                int lid = t + 256 * i;
                int r = lid >> 2, kq = lid & 3;
                sm.ld.feat[s2][kq * 4 + 0][r] = pf[i].x;
                sm.ld.feat[s2][kq * 4 + 1][r] = pf[i].y;
                sm.ld.feat[s2][kq * 4 + 2][r] = pf[i].z;
                sm.ld.feat[s2][kq * 4 + 3][r] = pf[i].w;
            }
#pragma unroll
            for (int i = 0; i < 5; i++) {
                int lid = t + 256 * i;
                int k = lid / 80, cc2 = lid - k * 80;
                sm.ld.w2[s2][k][cc2][0] = pw[i];
                sm.ld.w2[s2][k][cc2][1] = pw[i];
            }
        }
        __syncthreads();
    }

    // ---- stage accumulators in smem (aliases load buffers; all synced) ----
#pragma unroll
    for (int p = 0; p < 4; p++)
#pragma unroll
        for (int u = 0; u < 5; u++) {
            unsigned long long v = acc[p][u];
            sm.outs[ty * 8 + 2 * p + 0][tx * 5 + u] = __uint_as_float((unsigned)v);
            sm.outs[ty * 8 + 2 * p + 1][tx * 5 + u] = __uint_as_float((unsigned)(v >> 32));
        }
    __syncthreads();

    // ---- per-row max / argmax / exp-sum ----
    if (t < 128) {
        const int r = t;
        float mx = -1e30f;
        int   am = 0;
        for (int c2 = 0; c2 < Cc; c2++) {
            float v = sm.outs[r][c2] + bias_s[c2];
            if (v > mx) { mx = v; am = c2; }
        }
        float ssum = 0.0f;
        for (int c2 = 0; c2 < Cc; c2++)
            ssum += expf(sm.outs[r][c2] + bias_s[c2] - mx);
        rmax[r] = mx;
        rinv[r] = 1.0f / ssum;
        g_best[m0 + r] = am;
    }
    __syncthreads();

    // ---- coalesced softmax writes ----
    for (int idx = t; idx < 128 * Cc; idx += 256) {
        int r = idx / Cc, c2 = idx - r * Cc;
        out[(size_t)(m0 + r) * Cc + c2] =
            expf(sm.outs[r][c2] + bias_s[c2] - rmax[r]) * rinv[r];
    }
}

// ---------------------------------------------------------------------------
// CTC greedy collapse (smem-staged, coalesced): merge repeats, drop blank(77),
// pad to 30 with -1. Labels written value-cast to float after logits region.
// ---------------------------------------------------------------------------
__global__ __launch_bounds__(256)
void decode_kernel(float* __restrict__ out, size_t out_elems)
{
    __shared__ int sb[128 * Tlen];
    const int base_row = blockIdx.x * 128;
    for (int i = threadIdx.x; i < 128 * Tlen; i += 256)
        sb[i] = g_best[(size_t)base_row * Tlen + i];
    __syncthreads();

    const int b = threadIdx.x;
    if (b < 128) {
        size_t obase = LOGITS_ELEMS + (size_t)(base_row + b) * PRED;
        if (obase + PRED > out_elems) return;  // layout safety guard
        float* lab = out + obase;
        float buf[PRED];
#pragma unroll
        for (int i = 0; i < PRED; i++) buf[i] = -1.0f;
        int prev = -1, cnt = 0;
        const int* row = sb + b * Tlen;
#pragma unroll 4
        for (int tt = 0; tt < Tlen; tt++) {
            int v = row[tt];
            if (v != BLANKI && v != prev && cnt < PRED) buf[cnt++] = (float)v;
            prev = v;
        }
#pragma unroll
        for (int i = 0; i < PRED; i++) lab[i] = buf[i];
    }
}

extern "C" void kernel_launch(void* const* d_in, const int* in_sizes, int n_in,
                              void* d_out, int out_size)
{
    const float* feat = (const float*)d_in[0];  // [1024,80,512]
    const float* Wm   = (const float*)d_in[1];  // [512,78]
    const float* bias = (const float*)d_in[2];  // [78]
    float* out = (float*)d_out;

    gemm_softmax_kernel<<<Mrows / 128, 256>>>(feat, Wm, bias, out);
    decode_kernel<<<Bsz / 128, 256>>>(out, (size_t)out_size);
}

// round 4
// speedup vs baseline: 1.2263x; 1.2263x over previous
#include <cuda_runtime.h>
#include <cstdint>
#include <math.h>

// Problem constants
#define Bsz   1024
#define Tlen  80
#define Dd    512
#define Cc    78      // VOCAB+1
#define Mrows (Bsz*Tlen)   // 81920
#define BLANKI 77
#define PRED  30
#define LOGITS_ELEMS ((size_t)Mrows * Cc)  // 6,389,760

// argmax path scratch (static device global — no runtime alloc)
__device__ int g_best[Mrows];

// ---------------------------------------------------------------------------
// Fused GEMM (fp32, exact) + softmax + per-row argmax.
// Tile: 128 rows x 80 cols (78 real + 2 pad) per CTA, BK=16, double-buffered.
// 256 threads, each computes an 8x5 register tile.  (Round-1 mainloop, proven.)
// Epilogue computes exp exactly ONCE per logit (stored back to smem).
// ---------------------------------------------------------------------------
__global__ __launch_bounds__(256)
void gemm_softmax_kernel(const float* __restrict__ feat,
                         const float* __restrict__ Wm,
                         const float* __restrict__ bias,
                         float* __restrict__ out)
{
    __shared__ union {
        struct {
            float feat[2][16][128];  // [stage][k][row]
            float w[2][16][80];      // [stage][k][col]
        } ld;
        float outs[128][81];         // epilogue staging (81 = conflict-free col scans)
    } sm;
    __shared__ float bias_s[80];
    __shared__ float rinv[128];

    const int t  = threadIdx.x;
    const int tx = t & 15;        // col group: cols tx*5 .. tx*5+4
    const int ty = t >> 4;        // row group: rows ty*8 .. ty*8+7
    const int m0 = blockIdx.x * 128;

    if (t < 80) bias_s[t] = (t < Cc) ? bias[t] : 0.0f;

    float acc[8][5];
#pragma unroll
    for (int i = 0; i < 8; i++)
#pragma unroll
        for (int u = 0; u < 5; u++) acc[i][u] = 0.0f;

    // ---- load chunk 0 into stage 0 ----
    {
#pragma unroll
        for (int i = 0; i < 2; i++) {
            int lid = t + 256 * i;
            int r = lid >> 2, kq = lid & 3;
            float4 v = *reinterpret_cast<const float4*>(feat + (size_t)(m0 + r) * Dd + kq * 4);
            sm.ld.feat[0][kq * 4 + 0][r] = v.x;
            sm.ld.feat[0][kq * 4 + 1][r] = v.y;
            sm.ld.feat[0][kq * 4 + 2][r] = v.z;
            sm.ld.feat[0][kq * 4 + 3][r] = v.w;
        }
#pragma unroll
        for (int i = 0; i < 5; i++) {
            int lid = t + 256 * i;
            int k = lid / 80, cc2 = lid - k * 80;
            sm.ld.w[0][k][cc2] = (cc2 < Cc) ? Wm[(size_t)k * Cc + cc2] : 0.0f;
        }
    }
    __syncthreads();

    // ---- main loop over 32 K-chunks, single-sync double buffer ----
    for (int ch = 0; ch < 32; ++ch) {
        const int s = ch & 1;
        float4 pf[2];
        float  pw[5];
        if (ch < 31) {
            const int kb = (ch + 1) * 16;
#pragma unroll
            for (int i = 0; i < 2; i++) {
                int lid = t + 256 * i;
                int r = lid >> 2, kq = lid & 3;
                pf[i] = *reinterpret_cast<const float4*>(feat + (size_t)(m0 + r) * Dd + kb + kq * 4);
            }
#pragma unroll
            for (int i = 0; i < 5; i++) {
                int lid = t + 256 * i;
                int k = lid / 80, cc2 = lid - k * 80;
                pw[i] = (cc2 < Cc) ? Wm[(size_t)(kb + k) * Cc + cc2] : 0.0f;
            }
        }

#pragma unroll
        for (int kk = 0; kk < 16; kk++) {
            float4 a0 = *reinterpret_cast<const float4*>(&sm.ld.feat[s][kk][ty * 8]);
            float4 a1 = *reinterpret_cast<const float4*>(&sm.ld.feat[s][kk][ty * 8 + 4]);
            float bz[5];
#pragma unroll
            for (int u = 0; u < 5; u++) bz[u] = sm.ld.w[s][kk][tx * 5 + u];
            float av[8] = {a0.x, a0.y, a0.z, a0.w, a1.x, a1.y, a1.z, a1.w};
#pragma unroll
            for (int i = 0; i < 8; i++)
#pragma unroll
                for (int u = 0; u < 5; u++)
                    acc[i][u] += av[i] * bz[u];
        }

        if (ch < 31) {
            const int s2 = (ch + 1) & 1;
#pragma unroll
            for (int i = 0; i < 2; i++) {
                int lid = t + 256 * i;
                int r = lid >> 2, kq = lid & 3;
                sm.ld.feat[s2][kq * 4 + 0][r] = pf[i].x;
                sm.ld.feat[s2][kq * 4 + 1][r] = pf[i].y;
                sm.ld.feat[s2][kq * 4 + 2][r] = pf[i].z;
                sm.ld.feat[s2][kq * 4 + 3][r] = pf[i].w;
            }
#pragma unroll
            for (int i = 0; i < 5; i++) {
                int lid = t + 256 * i;
                int k = lid / 80, cc2 = lid - k * 80;
                sm.ld.w[s2][k][cc2] = pw[i];
            }
        }
        __syncthreads();
    }

    // ---- stage accumulators (+bias) in smem (aliases load buffers; synced) ----
#pragma unroll
    for (int i = 0; i < 8; i++)
#pragma unroll
        for (int u = 0; u < 5; u++)
            sm.outs[ty * 8 + i][tx * 5 + u] = acc[i][u] + bias_s[tx * 5 + u];
    __syncthreads();

    // ---- per-row: max/argmax, then exp ONCE (stored back), sum ----
    if (t < 128) {
        const int r = t;
        float mx = -1e30f;
        int   am = 0;
        for (int c2 = 0; c2 < Cc; c2++) {
            float v = sm.outs[r][c2];
            if (v > mx) { mx = v; am = c2; }
        }
        float ssum = 0.0f;
        for (int c2 = 0; c2 < Cc; c2++) {
            float e = __expf(sm.outs[r][c2] - mx);
            sm.outs[r][c2] = e;
            ssum += e;
        }
        rinv[r] = 1.0f / ssum;
        g_best[m0 + r] = am;
    }
    __syncthreads();

    // ---- coalesced softmax writes (no exp here) ----
    for (int idx = t; idx < 128 * Cc; idx += 256) {
        int r = idx / Cc, c2 = idx - r * Cc;
        out[(size_t)(m0 + r) * Cc + c2] = sm.outs[r][c2] * rinv[r];
    }
}

// ---------------------------------------------------------------------------
// CTC greedy collapse — one warp per row, ballot prefix-scan over 80 steps.
// Merge repeats, drop blank(77), pad to 30 with -1; labels value-cast to float.
// ---------------------------------------------------------------------------
__global__ __launch_bounds__(256)
void decode_kernel(float* __restrict__ out, size_t out_elems)
{
    const int warp = (blockIdx.x * blockDim.x + threadIdx.x) >> 5;  // row 0..1023
    const int lane = threadIdx.x & 31;
    if (warp >= Bsz) return;

    size_t obase = LOGITS_ELEMS + (size_t)warp * PRED;
    if (obase + PRED > out_elems) return;  // layout safety guard
    float* lab = out + obase;

    if (lane < PRED) lab[lane] = -1.0f;
    __syncwarp();  // order fill before scatter

    const int* row = g_best + (size_t)warp * Tlen;
    int prefix = 0;
    int carry  = -1;
#pragma unroll
    for (int seg = 0; seg < 3; seg++) {
        const int idx = seg * 32 + lane;
        const bool valid = (idx < Tlen);
        int v = valid ? row[idx] : BLANKI;
        int prev = __shfl_up_sync(0xFFFFFFFFu, v, 1);
        if (lane == 0) prev = carry;
        const bool keep = valid && (v != BLANKI) && (v != prev);
        const unsigned mask = __ballot_sync(0xFFFFFFFFu, keep);
        const int pos = prefix + __popc(mask & ((1u << lane) - 1u));
        if (keep && pos < PRED) lab[pos] = (float)v;
        prefix += __popc(mask);
        carry = __shfl_sync(0xFFFFFFFFu, v, 31);
    }
}

extern "C" void kernel_launch(void* const* d_in, const int* in_sizes, int n_in,
                              void* d_out, int out_size)
{
    const float* feat = (const float*)d_in[0];  // [1024,80,512]
    const float* Wm   = (const float*)d_in[1];  // [512,78]
    const float* bias = (const float*)d_in[2];  // [78]
    float* out = (float*)d_out;

    gemm_softmax_kernel<<<Mrows / 128, 256>>>(feat, Wm, bias, out);
    decode_kernel<<<(Bsz * 32) / 256, 256>>>(out, (size_t)out_size);
}

// round 5
// speedup vs baseline: 1.3232x; 1.0790x over previous
#include <cuda_runtime.h>
#include <cstdint>
#include <math.h>

// Problem constants
#define Bsz   1024
#define Tlen  80
#define Dd    512
#define Cc    78      // VOCAB+1
#define Mrows (Bsz*Tlen)   // 81920
#define BLANKI 77
#define PRED  30
#define LOGITS_ELEMS ((size_t)Mrows * Cc)  // 6,389,760

// argmax path scratch (static device global — no runtime alloc)
__device__ int g_best[Mrows];

// ---------------------------------------------------------------------------
// Fused GEMM (fp32, exact) + softmax + per-row argmax.
// Tile: 128 rows x 80 cols per CTA, BK=16, double-buffered. 256 threads,
// each computes an 8x5 register tile. Epilogue is fully register-resident:
// per-row reductions via half-warp shuffles (the 16 tx-threads of a row
// group are contiguous lanes), direct coalesced gmem writes, no smem staging.
// ---------------------------------------------------------------------------
__global__ __launch_bounds__(256)
void gemm_softmax_kernel(const float* __restrict__ feat,
                         const float* __restrict__ Wm,
                         const float* __restrict__ bias,
                         float* __restrict__ out)
{
    __shared__ struct {
        float feat[2][16][128];  // [stage][k][row]
        float w[2][16][80];      // [stage][k][col]
    } sm;
    __shared__ float bias_s[80];

    const int t  = threadIdx.x;
    const int tx = t & 15;        // col group: cols tx*5 .. tx*5+4
    const int ty = t >> 4;        // row group: rows ty*8 .. ty*8+7
    const int m0 = blockIdx.x * 128;

    if (t < 80) bias_s[t] = (t < Cc) ? bias[t] : 0.0f;

    float acc[8][5];
#pragma unroll
    for (int i = 0; i < 8; i++)
#pragma unroll
        for (int u = 0; u < 5; u++) acc[i][u] = 0.0f;

    // ---- load chunk 0 into stage 0 ----
    {
#pragma unroll
        for (int i = 0; i < 2; i++) {
            int lid = t + 256 * i;
            int r = lid >> 2, kq = lid & 3;
            float4 v = *reinterpret_cast<const float4*>(feat + (size_t)(m0 + r) * Dd + kq * 4);
            sm.feat[0][kq * 4 + 0][r] = v.x;
            sm.feat[0][kq * 4 + 1][r] = v.y;
            sm.feat[0][kq * 4 + 2][r] = v.z;
            sm.feat[0][kq * 4 + 3][r] = v.w;
        }
#pragma unroll
        for (int i = 0; i < 5; i++) {
            int lid = t + 256 * i;
            int k = lid / 80, cc2 = lid - k * 80;
            sm.w[0][k][cc2] = (cc2 < Cc) ? Wm[(size_t)k * Cc + cc2] : 0.0f;
        }
    }
    __syncthreads();

    // ---- main loop over 32 K-chunks, single-sync double buffer ----
    for (int ch = 0; ch < 32; ++ch) {
        const int s = ch & 1;
        float4 pf[2];
        float  pw[5];
        if (ch < 31) {
            const int kb = (ch + 1) * 16;
#pragma unroll
            for (int i = 0; i < 2; i++) {
                int lid = t + 256 * i;
                int r = lid >> 2, kq = lid & 3;
                pf[i] = *reinterpret_cast<const float4*>(feat + (size_t)(m0 + r) * Dd + kb + kq * 4);
            }
#pragma unroll
            for (int i = 0; i < 5; i++) {
                int lid = t + 256 * i;
                int k = lid / 80, cc2 = lid - k * 80;
                pw[i] = (cc2 < Cc) ? Wm[(size_t)(kb + k) * Cc + cc2] : 0.0f;
            }
        }

#pragma unroll
        for (int kk = 0; kk < 16; kk++) {
            float4 a0 = *reinterpret_cast<const float4*>(&sm.feat[s][kk][ty * 8]);
            float4 a1 = *reinterpret_cast<const float4*>(&sm.feat[s][kk][ty * 8 + 4]);
            float bz[5];
#pragma unroll
            for (int u = 0; u < 5; u++) bz[u] = sm.w[s][kk][tx * 5 + u];
            float av[8] = {a0.x, a0.y, a0.z, a0.w, a1.x, a1.y, a1.z, a1.w};
#pragma unroll
            for (int i = 0; i < 8; i++)
#pragma unroll
                for (int u = 0; u < 5; u++)
                    acc[i][u] += av[i] * bz[u];
        }

        if (ch < 31) {
            const int s2 = (ch + 1) & 1;
#pragma unroll
            for (int i = 0; i < 2; i++) {
                int lid = t + 256 * i;
                int r = lid >> 2, kq = lid & 3;
                sm.feat[s2][kq * 4 + 0][r] = pf[i].x;
                sm.feat[s2][kq * 4 + 1][r] = pf[i].y;
                sm.feat[s2][kq * 4 + 2][r] = pf[i].z;
                sm.feat[s2][kq * 4 + 3][r] = pf[i].w;
            }
#pragma unroll
            for (int i = 0; i < 5; i++) {
                int lid = t + 256 * i;
                int k = lid / 80, cc2 = lid - k * 80;
                sm.w[s2][k][cc2] = pw[i];
            }
        }
        __syncthreads();
    }

    // ---- register-resident epilogue: bias, max/argmax, exp, sum, write ----
    float bz[5];
#pragma unroll
    for (int u = 0; u < 5; u++) bz[u] = bias_s[tx * 5 + u];

#pragma unroll
    for (int i = 0; i < 8; i++) {
        const int row = m0 + ty * 8 + i;
        float v[5];
        float mx = -1e30f;
        int   am = 127;  // sentinel larger than any real col
#pragma unroll
        for (int u = 0; u < 5; u++) {
            const int c = tx * 5 + u;
            v[u] = acc[i][u] + bz[u];
            const bool real = (c < Cc);
            if (real && v[u] > mx) { mx = v[u]; am = c; }
        }
        // reduce max/argmax over the 16-lane group (first-max tie-break)
#pragma unroll
        for (int off = 1; off < 16; off <<= 1) {
            float omx = __shfl_xor_sync(0xFFFFFFFFu, mx, off);
            int   oam = __shfl_xor_sync(0xFFFFFFFFu, am, off);
            if (omx > mx || (omx == mx && oam < am)) { mx = omx; am = oam; }
        }
        // exp + sum
        float e[5];
        float ssum = 0.0f;
#pragma unroll
        for (int u = 0; u < 5; u++) {
            const int c = tx * 5 + u;
            e[u] = (c < Cc) ? __expf(v[u] - mx) : 0.0f;
            ssum += e[u];
        }
#pragma unroll
        for (int off = 1; off < 16; off <<= 1)
            ssum += __shfl_xor_sync(0xFFFFFFFFu, ssum, off);
        const float rinv = __frcp_rn(ssum);
        // coalesced row write: 16 lanes x 5 consecutive floats
        float* orow = out + (size_t)row * Cc + tx * 5;
#pragma unroll
        for (int u = 0; u < 5; u++)
            if (tx * 5 + u < Cc) orow[u] = e[u] * rinv;
        if (tx == 0) g_best[row] = am;
    }
}

// ---------------------------------------------------------------------------
// CTC greedy collapse — one warp per row, ballot prefix-scan over 80 steps.
// ---------------------------------------------------------------------------
__global__ __launch_bounds__(256)
void decode_kernel(float* __restrict__ out, size_t out_elems)
{
    const int warp = (blockIdx.x * blockDim.x + threadIdx.x) >> 5;  // row 0..1023
    const int lane = threadIdx.x & 31;
    if (warp >= Bsz) return;

    size_t obase = LOGITS_ELEMS + (size_t)warp * PRED;
    if (obase + PRED > out_elems) return;  // layout safety guard
    float* lab = out + obase;

    if (lane < PRED) lab[lane] = -1.0f;
    __syncwarp();  // order fill before scatter

    const int* row = g_best + (size_t)warp * Tlen;
    int prefix = 0;
    int carry  = -1;
#pragma unroll
    for (int seg = 0; seg < 3; seg++) {
        const int idx = seg * 32 + lane;
        const bool valid = (idx < Tlen);
        int v = valid ? row[idx] : BLANKI;
        int prev = __shfl_up_sync(0xFFFFFFFFu, v, 1);
        if (lane == 0) prev = carry;
        const bool keep = valid && (v != BLANKI) && (v != prev);
        const unsigned mask = __ballot_sync(0xFFFFFFFFu, keep);
        const int pos = prefix + __popc(mask & ((1u << lane) - 1u));
        if (keep && pos < PRED) lab[pos] = (float)v;
        prefix += __popc(mask);
        carry = __shfl_sync(0xFFFFFFFFu, v, 31);
    }
}

extern "C" void kernel_launch(void* const* d_in, const int* in_sizes, int n_in,
                              void* d_out, int out_size)
{
    const float* feat = (const float*)d_in[0];  // [1024,80,512]
    const float* Wm   = (const float*)d_in[1];  // [512,78]
    const float* bias = (const float*)d_in[2];  // [78]
    float* out = (float*)d_out;

    gemm_softmax_kernel<<<Mrows / 128, 256>>>(feat, Wm, bias, out);
    decode_kernel<<<(Bsz * 32) / 256, 256>>>(out, (size_t)out_size);
}

// round 6
// speedup vs baseline: 2.0464x; 1.5465x over previous
#include <cuda_runtime.h>
#include <cuda_bf16.h>
#include <cstdint>
#include <math.h>

// ---------------- problem constants ----------------
#define Bsz   1024
#define Tlen  80
#define Dd    512
#define Cc    78
#define Mrows (Bsz*Tlen)          // 81920
#define BLANKI 77
#define PRED  30
#define LOGITS_ELEMS ((size_t)Mrows * Cc)

// ---------------- tiling ----------------
#define BK    32                  // K per chunk (2 mma k-steps)
#define NCH   (Dd/BK)             // 16 chunks
#define AROW  40                  // bf16 row stride (32 data + 8 pad; 80B = 20 banks)
#define APL   (128*AROW*2)        // A plane bytes = 10240
#define BPL   (80*AROW*2)         // B plane bytes = 6400
#define BOFF  (3*APL)             // 30720
#define STAGE 50176               // >= 3*APL + 3*BPL = 49920
#define SMEM_BYTES (2*STAGE)      // 100352
#define LP    84                  // epilogue logits row stride (floats)

// ---------------- device scratch (static, no runtime alloc) ----------------
__device__ int  g_best[Mrows];
__device__ __nv_bfloat16 g_Ws[3][80][Dd];   // W^T limbs: [limb][n][k]

// ---------------- helpers ----------------
__device__ __forceinline__ void split3(float v, __nv_bfloat16& h0,
                                       __nv_bfloat16& h1, __nv_bfloat16& h2) {
    h0 = __float2bfloat16_rn(v);
    float r1 = v - __bfloat162float(h0);
    h1 = __float2bfloat16_rn(r1);
    float r2 = r1 - __bfloat162float(h1);
    h2 = __float2bfloat16_rn(r2);
}

__device__ __forceinline__ void mma16816(float c[4], const uint32_t a[4],
                                         const uint32_t b[2]) {
    asm volatile(
        "mma.sync.aligned.m16n8k16.row.col.f32.bf16.bf16.f32 "
        "{%0,%1,%2,%3}, {%4,%5,%6,%7}, {%8,%9}, {%0,%1,%2,%3};"
        : "+f"(c[0]), "+f"(c[1]), "+f"(c[2]), "+f"(c[3])
        : "r"(a[0]), "r"(a[1]), "r"(a[2]), "r"(a[3]), "r"(b[0]), "r"(b[1]));
}

__device__ __forceinline__ void cp_async16(void* dst_smem, const void* src) {
    uint32_t d = (uint32_t)__cvta_generic_to_shared(dst_smem);
    asm volatile("cp.async.cg.shared.global [%0], [%1], 16;" :: "r"(d), "l"(src));
}
#define CP_COMMIT() asm volatile("cp.async.commit_group;" ::: "memory")
#define CP_WAIT0()  asm volatile("cp.async.wait_group 0;" ::: "memory")

// ---------------- W prep: transpose + 3-way bf16 split ----------------
__global__ void prep_w(const float* __restrict__ Wm) {
    int i = blockIdx.x * blockDim.x + threadIdx.x;   // n*512 + k
    if (i >= 80 * Dd) return;
    int n = i >> 9, k = i & 511;
    float v = (n < Cc) ? Wm[(size_t)k * Cc + n] : 0.0f;
    __nv_bfloat16 h0, h1, h2;
    split3(v, h0, h1, h2);
    g_Ws[0][n][k] = h0; g_Ws[1][n][k] = h1; g_Ws[2][n][k] = h2;
}

// ---------------- fused mma GEMM + softmax + argmax ----------------
// CTA tile 128x80, 8 warps as (wm 0..3) x (wn 0..1): warp tile 32x40.
// Per k16-step: 2 m-atoms x 5 n-atoms, 6 limb passes {00,10,20,01,11,02}.
__global__ __launch_bounds__(256, 2)
void gemm_mma_kernel(const float* __restrict__ feat,
                     const float* __restrict__ bias,
                     float* __restrict__ out)
{
    extern __shared__ char dsm[];
    __shared__ float bias_s[80];
    __shared__ float rinv_s[128];

    const int t    = threadIdx.x;
    const int lane = t & 31;
    const int wid  = t >> 5;
    const int wm   = wid & 3;
    const int wn   = wid >> 2;
    const int gID  = lane >> 2;
    const int tid4 = lane & 3;
    const int m0   = blockIdx.x * 128;

    if (t < 80) bias_s[t] = (t < Cc) ? bias[t] : 0.0f;

    float acc[2][5][4];
#pragma unroll
    for (int i = 0; i < 2; i++)
#pragma unroll
        for (int j = 0; j < 5; j++)
#pragma unroll
            for (int q = 0; q < 4; q++) acc[i][j][q] = 0.0f;

    const float* featb = feat + (size_t)m0 * Dd;

    // ---- prologue: chunk 0 ----
    {
        char* aB = dsm;
        char* bB = dsm + BOFF;
#pragma unroll
        for (int i = 0; i < 4; i++) {
            const int idx = t + 256 * i;
            if (idx < 960) {
                const int p = idx / 320, rem = idx - p * 320;
                const int n = rem >> 2, q = rem & 3;
                cp_async16(bB + p * BPL + n * (AROW * 2) + q * 16,
                           &g_Ws[p][n][q * 8]);
            }
        }
        CP_COMMIT();
#pragma unroll
        for (int i = 0; i < 4; i++) {
            const int fidx = t + 256 * i;
            const int r = fidx >> 3, q = fidx & 7;
            float4 v = *reinterpret_cast<const float4*>(featb + (size_t)r * Dd + q * 4);
            const int off = r * (AROW * 2) + q * 8;
            __nv_bfloat16 x0, x1, x2, y0, y1, y2, z0, z1, z2, w0, w1, w2;
            split3(v.x, x0, x1, x2); split3(v.y, y0, y1, y2);
            split3(v.z, z0, z1, z2); split3(v.w, w0, w1, w2);
            *(__nv_bfloat162*)(aB + 0 * APL + off)     = __nv_bfloat162(x0, y0);
            *(__nv_bfloat162*)(aB + 0 * APL + off + 4) = __nv_bfloat162(z0, w0);
            *(__nv_bfloat162*)(aB + 1 * APL + off)     = __nv_bfloat162(x1, y1);
            *(__nv_bfloat162*)(aB + 1 * APL + off + 4) = __nv_bfloat162(z1, w1);
            *(__nv_bfloat162*)(aB + 2 * APL + off)     = __nv_bfloat162(x2, y2);
            *(__nv_bfloat162*)(aB + 2 * APL + off + 4) = __nv_bfloat162(z2, w2);
        }
        CP_WAIT0();
    }
    __syncthreads();

    // ---- main loop ----
    for (int ch = 0; ch < NCH; ++ch) {
        const int s = ch & 1;
        char* aB = dsm + s * STAGE;
        char* bB = aB + BOFF;

        float4 pf[4];
        if (ch < NCH - 1) {
            const int kb = (ch + 1) * BK;
#pragma unroll
            for (int i = 0; i < 4; i++) {
                const int fidx = t + 256 * i;
                const int r = fidx >> 3, q = fidx & 7;
                pf[i] = *reinterpret_cast<const float4*>(featb + (size_t)r * Dd + kb + q * 4);
            }
            char* bN = dsm + (s ^ 1) * STAGE + BOFF;
#pragma unroll
            for (int i = 0; i < 4; i++) {
                const int idx = t + 256 * i;
                if (idx < 960) {
                    const int p = idx / 320, rem = idx - p * 320;
                    const int n = rem >> 2, q = rem & 3;
                    cp_async16(bN + p * BPL + n * (AROW * 2) + q * 16,
                               &g_Ws[p][n][kb + q * 8]);
                }
            }
            CP_COMMIT();
        }

        // ---- 2 k-steps of 6-pass limb mma ----
#pragma unroll
        for (int k0 = 0; k0 < BK; k0 += 16) {
#pragma unroll
            for (int bj = 0; bj < 3; bj++) {
                uint32_t b[5][2];
#pragma unroll
                for (int j = 0; j < 5; j++) {
                    const int n = wn * 40 + j * 8 + gID;
                    const char* p = bB + bj * BPL + n * (AROW * 2) + (k0 + tid4 * 2) * 2;
                    b[j][0] = *(const uint32_t*)p;
                    b[j][1] = *(const uint32_t*)(p + 16);
                }
                const int na = (bj == 0) ? 3 : (bj == 1) ? 2 : 1;
                for (int ai = 0; ai < na; ai++) {
#pragma unroll
                    for (int i = 0; i < 2; i++) {
                        const int row = wm * 32 + i * 16 + gID;
                        const char* p = aB + ai * APL + row * (AROW * 2) + (k0 + tid4 * 2) * 2;
                        uint32_t a[4];
                        a[0] = *(const uint32_t*)p;
                        a[1] = *(const uint32_t*)(p + 8 * (AROW * 2));
                        a[2] = *(const uint32_t*)(p + 16);
                        a[3] = *(const uint32_t*)(p + 8 * (AROW * 2) + 16);
#pragma unroll
                        for (int j = 0; j < 5; j++)
                            mma16816(acc[i][j], a, b[j]);
                    }
                }
            }
        }

        if (ch < NCH - 1) {
            char* aN = dsm + (s ^ 1) * STAGE;
#pragma unroll
            for (int i = 0; i < 4; i++) {
                const int fidx = t + 256 * i;
                const int r = fidx >> 3, q = fidx & 7;
                float4 v = pf[i];
                const int off = r * (AROW * 2) + q * 8;
                __nv_bfloat16 x0, x1, x2, y0, y1, y2, z0, z1, z2, w0, w1, w2;
                split3(v.x, x0, x1, x2); split3(v.y, y0, y1, y2);
                split3(v.z, z0, z1, z2); split3(v.w, w0, w1, w2);
                *(__nv_bfloat162*)(aN + 0 * APL + off)     = __nv_bfloat162(x0, y0);
                *(__nv_bfloat162*)(aN + 0 * APL + off + 4) = __nv_bfloat162(z0, w0);
                *(__nv_bfloat162*)(aN + 1 * APL + off)     = __nv_bfloat162(x1, y1);
                *(__nv_bfloat162*)(aN + 1 * APL + off + 4) = __nv_bfloat162(z1, w1);
                *(__nv_bfloat162*)(aN + 2 * APL + off)     = __nv_bfloat162(x2, y2);
                *(__nv_bfloat162*)(aN + 2 * APL + off + 4) = __nv_bfloat162(z2, w2);
            }
            CP_WAIT0();
        }
        __syncthreads();
    }

    // ---- stage logits (+bias) to smem ----
    float* L = (float*)dsm;
#pragma unroll
    for (int i = 0; i < 2; i++)
#pragma unroll
        for (int j = 0; j < 5; j++) {
            const int r0 = wm * 32 + i * 16 + gID;
            const int c0 = wn * 40 + j * 8 + tid4 * 2;
            L[r0 * LP + c0]           = acc[i][j][0] + bias_s[c0];
            L[r0 * LP + c0 + 1]       = acc[i][j][1] + bias_s[c0 + 1];
            L[(r0 + 8) * LP + c0]     = acc[i][j][2] + bias_s[c0];
            L[(r0 + 8) * LP + c0 + 1] = acc[i][j][3] + bias_s[c0 + 1];
        }
    __syncthreads();

    // ---- softmax + argmax: 2 threads per row (39 cols each) ----
    {
        const int r = t >> 1, h = t & 1;
        const int cb = h * 39;
        float mx = -1e30f; int am = 127;
        for (int c = 0; c < 39; c++) {
            float v = L[r * LP + cb + c];
            if (v > mx) { mx = v; am = cb + c; }
        }
        float omx = __shfl_xor_sync(0xFFFFFFFFu, mx, 1);
        int   oam = __shfl_xor_sync(0xFFFFFFFFu, am, 1);
        if (omx > mx || (omx == mx && oam < am)) { mx = omx; am = oam; }
        float ssum = 0.0f;
        for (int c = 0; c < 39; c++) {
            float e = __expf(L[r * LP + cb + c] - mx);
            L[r * LP + cb + c] = e;
            ssum += e;
        }
        ssum += __shfl_xor_sync(0xFFFFFFFFu, ssum, 1);
        if (h == 0) {
            rinv_s[r] = __frcp_rn(ssum);
            g_best[m0 + r] = am;
        }
    }
    __syncthreads();

    // ---- coalesced writes ----
    for (int idx = t; idx < 128 * Cc; idx += 256) {
        const int r = idx / Cc, c = idx - r * Cc;
        out[(size_t)(m0 + r) * Cc + c] = L[r * LP + c] * rinv_s[r];
    }
}

// ---------------- CTC greedy collapse (warp-ballot, proven) ----------------
__global__ __launch_bounds__(256)
void decode_kernel(float* __restrict__ out, size_t out_elems)
{
    const int warp = (blockIdx.x * blockDim.x + threadIdx.x) >> 5;
    const int lane = threadIdx.x & 31;
    if (warp >= Bsz) return;

    size_t obase = LOGITS_ELEMS + (size_t)warp * PRED;
    if (obase + PRED > out_elems) return;
    float* lab = out + obase;

    if (lane < PRED) lab[lane] = -1.0f;
    __syncwarp();

    const int* row = g_best + (size_t)warp * Tlen;
    int prefix = 0;
    int carry  = -1;
#pragma unroll
    for (int seg = 0; seg < 3; seg++) {
        const int idx = seg * 32 + lane;
        const bool valid = (idx < Tlen);
        int v = valid ? row[idx] : BLANKI;
        int prev = __shfl_up_sync(0xFFFFFFFFu, v, 1);
        if (lane == 0) prev = carry;
        const bool keep = valid && (v != BLANKI) && (v != prev);
        const unsigned mask = __ballot_sync(0xFFFFFFFFu, keep);
        const int pos = prefix + __popc(mask & ((1u << lane) - 1u));
        if (keep && pos < PRED) lab[pos] = (float)v;
        prefix += __popc(mask);
        carry = __shfl_sync(0xFFFFFFFFu, v, 31);
    }
}

// ---------------- launch ----------------
extern "C" void kernel_launch(void* const* d_in, const int* in_sizes, int n_in,
                              void* d_out, int out_size)
{
    const float* feat = (const float*)d_in[0];  // [1024,80,512]
    const float* Wm   = (const float*)d_in[1];  // [512,78]
    const float* bias = (const float*)d_in[2];  // [78]
    float* out = (float*)d_out;

    cudaFuncSetAttribute(gemm_mma_kernel,
                         cudaFuncAttributeMaxDynamicSharedMemorySize, SMEM_BYTES);

    prep_w<<<(80 * Dd + 255) / 256, 256>>>(Wm);
    gemm_mma_kernel<<<Mrows / 128, 256, SMEM_BYTES>>>(feat, bias, out);
    decode_kernel<<<(Bsz * 32) / 256, 256>>>(out, (size_t)out_size);
}

// round 7
// speedup vs baseline: 2.1740x; 1.0623x over previous
#include <cuda_runtime.h>
#include <cuda_bf16.h>
#include <cstdint>
#include <math.h>

// ---------------- problem constants ----------------
#define Bsz   1024
#define Tlen  80
#define Dd    512
#define Cc    78
#define Mrows (Bsz*Tlen)          // 81920
#define BLANKI 77
#define PRED  30
#define LOGITS_ELEMS ((size_t)Mrows * Cc)

// ---------------- tiling ----------------
#define BK    32                  // K per chunk (2 mma k-steps)
#define NCH   (Dd/BK)             // 16 chunks
#define AROW  40                  // bf16 row stride (32 data + 8 pad; 80B, ldmatrix conflict-free)
#define APL   (128*AROW*2)        // A plane bytes = 10240
#define BPL   (80*AROW*2)         // B plane bytes = 6400
#define BOFF  (3*APL)             // 30720
#define STAGE 50176               // >= 3*APL + 3*BPL = 49920
#define SMEM_BYTES (2*STAGE)      // 100352
#define LP    84                  // epilogue logits row stride (floats)

// ---------------- device scratch (static, no runtime alloc) ----------------
__device__ int  g_best[Mrows];
__device__ __nv_bfloat16 g_Ws[3][80][Dd];   // W^T limbs: [limb][n][k]

// ---------------- helpers ----------------
__device__ __forceinline__ void split3(float v, __nv_bfloat16& h0,
                                       __nv_bfloat16& h1, __nv_bfloat16& h2) {
    h0 = __float2bfloat16_rn(v);
    float r1 = v - __bfloat162float(h0);
    h1 = __float2bfloat16_rn(r1);
    float r2 = r1 - __bfloat162float(h1);
    h2 = __float2bfloat16_rn(r2);
}

// paired split: (x,y) -> 3 packed bf16x2 limbs (x low half, y high half)
__device__ __forceinline__ void split3x2(float x, float y,
                                         uint32_t& p0, uint32_t& p1, uint32_t& p2) {
    __nv_bfloat162 h0 = __float22bfloat162_rn(make_float2(x, y));
    float2 f0 = __bfloat1622float2(h0);
    float rx = x - f0.x, ry = y - f0.y;
    __nv_bfloat162 h1 = __float22bfloat162_rn(make_float2(rx, ry));
    float2 f1 = __bfloat1622float2(h1);
    __nv_bfloat162 h2 = __float22bfloat162_rn(make_float2(rx - f1.x, ry - f1.y));
    p0 = *reinterpret_cast<uint32_t*>(&h0);
    p1 = *reinterpret_cast<uint32_t*>(&h1);
    p2 = *reinterpret_cast<uint32_t*>(&h2);
}

__device__ __forceinline__ void mma16816(float c[4], const uint32_t a[4],
                                         const uint32_t b[2]) {
    asm volatile(
        "mma.sync.aligned.m16n8k16.row.col.f32.bf16.bf16.f32 "
        "{%0,%1,%2,%3}, {%4,%5,%6,%7}, {%8,%9}, {%0,%1,%2,%3};"
        : "+f"(c[0]), "+f"(c[1]), "+f"(c[2]), "+f"(c[3])
        : "r"(a[0]), "r"(a[1]), "r"(a[2]), "r"(a[3]), "r"(b[0]), "r"(b[1]));
}

#define LDMX4(r, addr) \
    asm volatile("ldmatrix.sync.aligned.m8n8.x4.shared.b16 {%0,%1,%2,%3}, [%4];" \
        : "=r"((r)[0]), "=r"((r)[1]), "=r"((r)[2]), "=r"((r)[3]) : "r"(addr))
#define LDMX4P(r0, r1, addr) \
    asm volatile("ldmatrix.sync.aligned.m8n8.x4.shared.b16 {%0,%1,%2,%3}, [%4];" \
        : "=r"((r0)[0]), "=r"((r0)[1]), "=r"((r1)[0]), "=r"((r1)[1]) : "r"(addr))
#define LDMX2(r, addr) \
    asm volatile("ldmatrix.sync.aligned.m8n8.x2.shared.b16 {%0,%1}, [%2];" \
        : "=r"((r)[0]), "=r"((r)[1]) : "r"(addr))

__device__ __forceinline__ void cp_async16(uint32_t dst_smem, const void* src) {
    asm volatile("cp.async.cg.shared.global [%0], [%1], 16;" :: "r"(dst_smem), "l"(src));
}
#define CP_COMMIT() asm volatile("cp.async.commit_group;" ::: "memory")
#define CP_WAIT0()  asm volatile("cp.async.wait_group 0;" ::: "memory")

// ---------------- W prep: transpose + 3-way bf16 split ----------------
__global__ void prep_w(const float* __restrict__ Wm) {
    int i = blockIdx.x * blockDim.x + threadIdx.x;   // n*512 + k
    if (i >= 80 * Dd) return;
    int n = i >> 9, k = i & 511;
    float v = (n < Cc) ? Wm[(size_t)k * Cc + n] : 0.0f;
    __nv_bfloat16 h0, h1, h2;
    split3(v, h0, h1, h2);
    g_Ws[0][n][k] = h0; g_Ws[1][n][k] = h1; g_Ws[2][n][k] = h2;
}

// ---------------- fused mma GEMM + softmax + argmax ----------------
// CTA tile 128x80, 8 warps as (wm 0..3) x (wn 0..1): warp tile 32x40.
// Per k16-step: 6 limb passes {a0b0,a1b0,a2b0,a0b1,a1b1,a0b2},
// fragments loaded via ldmatrix (A hoisted across B limbs).
__global__ __launch_bounds__(256, 2)
void gemm_mma_kernel(const float* __restrict__ feat,
                     const float* __restrict__ bias,
                     float* __restrict__ out)
{
    extern __shared__ char dsm[];
    __shared__ float bias_s[80];
    __shared__ float rinv_s[128];

    const int t    = threadIdx.x;
    const int lane = t & 31;
    const int wid  = t >> 5;
    const int wm   = wid & 3;
    const int wn   = wid >> 2;
    const int gID  = lane >> 2;
    const int tid4 = lane & 3;
    const int m0   = blockIdx.x * 128;
    const uint32_t dsmu = (uint32_t)__cvta_generic_to_shared(dsm);

    if (t < 80) bias_s[t] = (t < Cc) ? bias[t] : 0.0f;

    // ldmatrix per-lane address offsets (within plane)
    const uint32_t aoff0 = (uint32_t)((wm * 32 + (lane & 15)) * (AROW * 2) + (lane >> 4) * 16);
    const uint32_t aoff1 = aoff0 + 16 * (AROW * 2);
    const uint32_t boff0 = (uint32_t)((wn * 40 + (lane >> 4) * 8 + (lane & 7)) * (AROW * 2)
                                      + ((lane >> 3) & 1) * 16);
    const uint32_t boff2 = boff0 + 16 * (AROW * 2);
    const uint32_t boff4 = (uint32_t)((wn * 40 + 32 + (lane & 7)) * (AROW * 2)
                                      + ((lane >> 3) & 1) * 16);

    float acc[2][5][4];
#pragma unroll
    for (int i = 0; i < 2; i++)
#pragma unroll
        for (int j = 0; j < 5; j++)
#pragma unroll
            for (int q = 0; q < 4; q++) acc[i][j][q] = 0.0f;

    const float* featb = feat + (size_t)m0 * Dd;

    // ---- A store: split fp32 float4 -> 3 bf16 planes (packed stores) ----
    auto storeA = [&](uint32_t aBu_g, char* aB, int fidx, float4 v) {
        (void)aBu_g;
        const int r = fidx >> 3, q = fidx & 7;
        const int off = r * (AROW * 2) + q * 8;
        uint32_t p0a, p1a, p2a, p0b, p1b, p2b;
        split3x2(v.x, v.y, p0a, p1a, p2a);
        split3x2(v.z, v.w, p0b, p1b, p2b);
        *(uint32_t*)(aB + 0 * APL + off)     = p0a;
        *(uint32_t*)(aB + 0 * APL + off + 4) = p0b;
        *(uint32_t*)(aB + 1 * APL + off)     = p1a;
        *(uint32_t*)(aB + 1 * APL + off + 4) = p1b;
        *(uint32_t*)(aB + 2 * APL + off)     = p2a;
        *(uint32_t*)(aB + 2 * APL + off + 4) = p2b;
    };

    // ---- prologue: chunk 0 ----
    {
        char* aB = dsm;
        const uint32_t bBu = dsmu + BOFF;
#pragma unroll
        for (int i = 0; i < 4; i++) {
            const int idx = t + 256 * i;
            if (idx < 960) {
                const int p = idx / 320, rem = idx - p * 320;
                const int n = rem >> 2, q = rem & 3;
                cp_async16(bBu + p * BPL + n * (AROW * 2) + q * 16,
                           &g_Ws[p][n][q * 8]);
            }
        }
        CP_COMMIT();
#pragma unroll
        for (int i = 0; i < 4; i++) {
            const int fidx = t + 256 * i;
            const int r = fidx >> 3, q = fidx & 7;
            float4 v = *reinterpret_cast<const float4*>(featb + (size_t)r * Dd + q * 4);
            storeA(0, aB, fidx, v);
        }
        CP_WAIT0();
    }
    __syncthreads();

    // ---- main loop ----
    for (int ch = 0; ch < NCH; ++ch) {
        const int s = ch & 1;
        const uint32_t aBu = dsmu + s * STAGE;
        const uint32_t bBu = aBu + BOFF;

        float4 pf[4];
        if (ch < NCH - 1) {
            const int kb = (ch + 1) * BK;
#pragma unroll
            for (int i = 0; i < 4; i++) {
                const int fidx = t + 256 * i;
                const int r = fidx >> 3, q = fidx & 7;
                pf[i] = *reinterpret_cast<const float4*>(featb + (size_t)r * Dd + kb + q * 4);
            }
            const uint32_t bNu = dsmu + (s ^ 1) * STAGE + BOFF;
#pragma unroll
            for (int i = 0; i < 4; i++) {
                const int idx = t + 256 * i;
                if (idx < 960) {
                    const int p = idx / 320, rem = idx - p * 320;
                    const int n = rem >> 2, q = rem & 3;
                    cp_async16(bNu + p * BPL + n * (AROW * 2) + q * 16,
                               &g_Ws[p][n][kb + q * 8]);
                }
            }
            CP_COMMIT();
        }

        // ---- 2 k-steps of 6-pass limb mma (ldmatrix fragments) ----
#pragma unroll
        for (int k0 = 0; k0 < 2; k0++) {
            const uint32_t kb = k0 * 32;          // 16 bf16 = 32 bytes
            uint32_t afr[3][2][4];
#pragma unroll
            for (int ai = 0; ai < 3; ai++) {
                LDMX4(afr[ai][0], aBu + ai * APL + aoff0 + kb);
                LDMX4(afr[ai][1], aBu + ai * APL + aoff1 + kb);
            }
#pragma unroll
            for (int bj = 0; bj < 3; bj++) {
                uint32_t b[5][2];
                LDMX4P(b[0], b[1], bBu + bj * BPL + boff0 + kb);
                LDMX4P(b[2], b[3], bBu + bj * BPL + boff2 + kb);
                LDMX2(b[4],        bBu + bj * BPL + boff4 + kb);
#pragma unroll
                for (int ai = 0; ai <= 2 - bj; ai++)
#pragma unroll
                    for (int i = 0; i < 2; i++)
#pragma unroll
                        for (int j = 0; j < 5; j++)
                            mma16816(acc[i][j], afr[ai][i], b[j]);
            }
        }

        if (ch < NCH - 1) {
            char* aN = dsm + (s ^ 1) * STAGE;
#pragma unroll
            for (int i = 0; i < 4; i++) storeA(0, aN, t + 256 * i, pf[i]);
            CP_WAIT0();
        }
        __syncthreads();
    }

    // ---- stage logits (+bias) to smem ----
    float* L = (float*)dsm;
#pragma unroll
    for (int i = 0; i < 2; i++)
#pragma unroll
        for (int j = 0; j < 5; j++) {
            const int r0 = wm * 32 + i * 16 + gID;
            const int c0 = wn * 40 + j * 8 + tid4 * 2;
            L[r0 * LP + c0]           = acc[i][j][0] + bias_s[c0];
            L[r0 * LP + c0 + 1]       = acc[i][j][1] + bias_s[c0 + 1];
            L[(r0 + 8) * LP + c0]     = acc[i][j][2] + bias_s[c0];
            L[(r0 + 8) * LP + c0 + 1] = acc[i][j][3] + bias_s[c0 + 1];
        }
    __syncthreads();

    // ---- softmax + argmax: 2 threads per row (39 cols each) ----
    {
        const int r = t >> 1, h = t & 1;
        const int cb = h * 39;
        float mx = -1e30f; int am = 127;
        for (int c = 0; c < 39; c++) {
            float v = L[r * LP + cb + c];
            if (v > mx) { mx = v; am = cb + c; }
        }
        float omx = __shfl_xor_sync(0xFFFFFFFFu, mx, 1);
        int   oam = __shfl_xor_sync(0xFFFFFFFFu, am, 1);
        if (omx > mx || (omx == mx && oam < am)) { mx = omx; am = oam; }
        float ssum = 0.0f;
        for (int c = 0; c < 39; c++) {
            float e = __expf(L[r * LP + cb + c] - mx);
            L[r * LP + cb + c] = e;
            ssum += e;
        }
        ssum += __shfl_xor_sync(0xFFFFFFFFu, ssum, 1);
        if (h == 0) {
            rinv_s[r] = __frcp_rn(ssum);
            g_best[m0 + r] = am;
        }
    }
    __syncthreads();

    // ---- coalesced writes ----
    for (int idx = t; idx < 128 * Cc; idx += 256) {
        const int r = idx / Cc, c = idx - r * Cc;
        out[(size_t)(m0 + r) * Cc + c] = L[r * LP + c] * rinv_s[r];
    }
}

// ---------------- CTC greedy collapse (warp-ballot, proven) ----------------
__global__ __launch_bounds__(256)
void decode_kernel(float* __restrict__ out, size_t out_elems)
{
    const int warp = (blockIdx.x * blockDim.x + threadIdx.x) >> 5;
    const int lane = threadIdx.x & 31;
    if (warp >= Bsz) return;

    size_t obase = LOGITS_ELEMS + (size_t)warp * PRED;
    if (obase + PRED > out_elems) return;
    float* lab = out + obase;

    if (lane < PRED) lab[lane] = -1.0f;
    __syncwarp();

    const int* row = g_best + (size_t)warp * Tlen;
    int prefix = 0;
    int carry  = -1;
#pragma unroll
    for (int seg = 0; seg < 3; seg++) {
        const int idx = seg * 32 + lane;
        const bool valid = (idx < Tlen);
        int v = valid ? row[idx] : BLANKI;
        int prev = __shfl_up_sync(0xFFFFFFFFu, v, 1);
        if (lane == 0) prev = carry;
        const bool keep = valid && (v != BLANKI) && (v != prev);
        const unsigned mask = __ballot_sync(0xFFFFFFFFu, keep);
        const int pos = prefix + __popc(mask & ((1u << lane) - 1u));
        if (keep && pos < PRED) lab[pos] = (float)v;
        prefix += __popc(mask);
        carry = __shfl_sync(0xFFFFFFFFu, v, 31);
    }
}

// ---------------- launch ----------------
extern "C" void kernel_launch(void* const* d_in, const int* in_sizes, int n_in,
                              void* d_out, int out_size)
{
    const float* feat = (const float*)d_in[0];  // [1024,80,512]
    const float* Wm   = (const float*)d_in[1];  // [512,78]
    const float* bias = (const float*)d_in[2];  // [78]
    float* out = (float*)d_out;

    cudaFuncSetAttribute(gemm_mma_kernel,
                         cudaFuncAttributeMaxDynamicSharedMemorySize, SMEM_BYTES);

    prep_w<<<(80 * Dd + 255) / 256, 256>>>(Wm);
    gemm_mma_kernel<<<Mrows / 128, 256, SMEM_BYTES>>>(feat, bias, out);
    decode_kernel<<<(Bsz * 32) / 256, 256>>>(out, (size_t)out_size);
}